// round 1
// baseline (speedup 1.0000x reference)
#include <cuda_runtime.h>
#include <math.h>

// FlashCrossAttentionV2: B=2, Sq=Sk=2048, H=16, D=64, window = (256,256),
// causal=0, use_window_mask=1 (fixed by setup_inputs). fp32 in/out.
//
// Baseline SIMT flash-attention with sliding-window tile pruning.
// Layout: q [B,Sq,H,D], kv [B,Sk,2,H,D], out [B,Sq,H,D].

#define TQ   64
#define TK   64
#define DD   64
#define WIN  256
#define SQ   2048
#define SKK  2048
#define HH   16
#define SST  68          // smem row stride in floats (17 float4) — conflict-free
#define SCALE 0.125f     // 1/sqrt(64)

__global__ __launch_bounds__(256, 3)
void fa_window_kernel(const float* __restrict__ q,
                      const float* __restrict__ kv,
                      float* __restrict__ out)
{
    extern __shared__ float sm[];
    float* Qs = sm;                  // [64][68]
    float* Ks = Qs + TQ * SST;       // [64][68]
    float* Vs = Ks + TK * SST;       // [64][68]
    float* Ps = Vs + TK * SST;       // [64][68]

    const int tid = threadIdx.x;
    const int q0  = blockIdx.x * TQ;
    const int h   = blockIdx.y;
    const int b   = blockIdx.z;

    // ---- load Q tile (coalesced float4) ----
    const float* qbase = q + (((size_t)b * SQ + q0) * HH + h) * DD;
    for (int idx = tid; idx < TQ * 16; idx += 256) {
        int r = idx >> 4, c = idx & 15;
        float4 v = *reinterpret_cast<const float4*>(qbase + (size_t)r * HH * DD + c * 4);
        *reinterpret_cast<float4*>(Qs + r * SST + c * 4) = v;
    }

    const int qi = tid >> 2;   // query within tile: 0..63
    const int g  = tid & 3;    // 4 lanes cooperate per query
    const int qg = q0 + qi;    // global query index

    float m = -1e30f, l = 0.0f;
    float4 acc[4];
    #pragma unroll
    for (int j = 0; j < 4; j++) acc[j] = make_float4(0.f, 0.f, 0.f, 0.f);

    // key range covered by this query tile's window (tile-aligned since WIN%64==0)
    int kt0 = q0 - WIN;      if (kt0 < 0)   kt0 = 0;
    int kt1 = q0 + TQ + WIN; if (kt1 > SKK) kt1 = SKK;

    const size_t kvrow = (size_t)2 * HH * DD;   // kv stride along seq

    for (int k0 = kt0; k0 < kt1; k0 += TK) {
        // ---- load K and V tiles ----
        const float* kbase = kv + (((((size_t)b * SKK + k0) * 2 + 0) * HH + h)) * DD;
        const float* vbase = kv + (((((size_t)b * SKK + k0) * 2 + 1) * HH + h)) * DD;
        for (int idx = tid; idx < TK * 16; idx += 256) {
            int r = idx >> 4, c = idx & 15;
            float4 kvv = *reinterpret_cast<const float4*>(kbase + (size_t)r * kvrow + c * 4);
            *reinterpret_cast<float4*>(Ks + r * SST + c * 4) = kvv;
            float4 vvv = *reinterpret_cast<const float4*>(vbase + (size_t)r * kvrow + c * 4);
            *reinterpret_cast<float4*>(Vs + r * SST + c * 4) = vvv;
        }
        __syncthreads();

        // ---- S = Q @ K^T for my 16 keys (keys j*4+g) ----
        float s[16];
        #pragma unroll
        for (int j = 0; j < 16; j++) s[j] = 0.f;

        const float4* Qr = reinterpret_cast<const float4*>(Qs + qi * SST);
        #pragma unroll 4
        for (int d4 = 0; d4 < 16; d4++) {
            float4 qv = Qr[d4];
            #pragma unroll
            for (int j = 0; j < 16; j++) {
                int row = j * 4 + g;
                float4 kk = *reinterpret_cast<const float4*>(Ks + row * SST + d4 * 4);
                s[j] += qv.x * kk.x + qv.y * kk.y + qv.z * kk.z + qv.w * kk.w;
            }
        }

        // ---- window mask + online softmax ----
        float tmax = -1e30f;
        #pragma unroll
        for (int j = 0; j < 16; j++) {
            int kgl = k0 + j * 4 + g;
            int dlt = kgl - qg;
            bool vis = (dlt >= -WIN) && (dlt <= WIN);
            s[j] = vis ? s[j] * SCALE : -1e30f;
            tmax = fmaxf(tmax, s[j]);
        }
        tmax = fmaxf(tmax, __shfl_xor_sync(0xffffffffu, tmax, 1));
        tmax = fmaxf(tmax, __shfl_xor_sync(0xffffffffu, tmax, 2));

        float newm = fmaxf(m, tmax);
        float corr = __expf(m - newm);
        float lsum = 0.f;
        #pragma unroll
        for (int j = 0; j < 16; j++) {
            float p = __expf(s[j] - newm);
            Ps[qi * SST + j * 4 + g] = p;
            lsum += p;
        }
        lsum += __shfl_xor_sync(0xffffffffu, lsum, 1);
        lsum += __shfl_xor_sync(0xffffffffu, lsum, 2);
        l = l * corr + lsum;
        m = newm;
        #pragma unroll
        for (int j = 0; j < 4; j++) {
            acc[j].x *= corr; acc[j].y *= corr; acc[j].z *= corr; acc[j].w *= corr;
        }
        __syncwarp();   // P rows for my qi are produced within this warp

        // ---- O += P @ V  (my dim chunks: (j*4+g)*4 .. +3) ----
        #pragma unroll 8
        for (int k = 0; k < TK; k++) {
            float p = Ps[qi * SST + k];
            #pragma unroll
            for (int j = 0; j < 4; j++) {
                float4 vv = *reinterpret_cast<const float4*>(Vs + k * SST + (j * 4 + g) * 4);
                acc[j].x += p * vv.x; acc[j].y += p * vv.y;
                acc[j].z += p * vv.z; acc[j].w += p * vv.w;
            }
        }
        __syncthreads();  // before K/V/P smem reuse
    }

    // ---- normalize and store ----
    float inv = 1.0f / l;
    float* obase = out + (((size_t)b * SQ + qg) * HH + h) * DD;
    #pragma unroll
    for (int j = 0; j < 4; j++) {
        float4 o;
        o.x = acc[j].x * inv; o.y = acc[j].y * inv;
        o.z = acc[j].z * inv; o.w = acc[j].w * inv;
        *reinterpret_cast<float4*>(obase + (j * 4 + g) * 4) = o;
    }
}

extern "C" void kernel_launch(void* const* d_in, const int* in_sizes, int n_in,
                              void* d_out, int out_size)
{
    const float* q  = (const float*)d_in[0];
    const float* kv = (const float*)d_in[1];
    float* out = (float*)d_out;

    int B = in_sizes[0] / (SQ * HH * DD);

    size_t smem = (size_t)4 * TQ * SST * sizeof(float);   // 69632 B
    cudaFuncSetAttribute(fa_window_kernel,
                         cudaFuncAttributeMaxDynamicSharedMemorySize, (int)smem);

    dim3 grid(SQ / TQ, HH, B);
    fa_window_kernel<<<grid, 256, smem>>>(q, kv, out);
}

// round 3
// speedup vs baseline: 2.0675x; 2.0675x over previous
#include <cuda_runtime.h>
#include <stdint.h>

// FlashCrossAttentionV2 SIMT GEMM-style: B=2, Sq=Sk=2048, H=16, D=64,
// window=(256,256). fp32 throughout.
// CTA: 256 threads, TQ=128 queries, TK=128 keys/tile (window -> <=5 tiles).
// QK: 16x16 thread grid, 8q x 8k register tile, scalar FFMA.
// PV: 128 positions (8d-block x 16 q-block) x 2 k-halves (split-K),
//     8q x 8d register tile, packed fma.rn.f32x2 over d-pairs.
// smem XOR-swizzled at float4 granularity: g' = g ^ ((row>>3)&7).

#define SEQ  2048
#define NH   16
#define DIM  64
#define WIN  256
#define TQ   128
#define TK   128
#define SCALE 0.125f

// smem float offsets
#define OQ 0          // Q: 128 x 64
#define OK 8192       // K: 128 x 64
#define OV 16384      // V: 128 x 64
#define OP 24576      // P_T: 128(k) x 128(q)  (also merge staging)
#define OC 40960      // corr[128]
#define OL 41088      // linv[128]
#define SMF 41216     // floats -> 164864 bytes

// swizzled float index; row stride 16 float4 (Q/K/V) or 32 (P_T)
static __device__ __forceinline__ int ixq(int r, int g) {
    return (r * 16 + (g ^ ((r >> 3) & 7))) * 4;
}
static __device__ __forceinline__ int ixp(int r, int g) {
    return (r * 32 + (g ^ ((r >> 3) & 7))) * 4;
}

static __device__ __forceinline__ unsigned long long pk2(float x) {
    unsigned long long r;
    asm("mov.b64 %0, {%1,%1};" : "=l"(r) : "f"(x));
    return r;
}
static __device__ __forceinline__ void fma2(unsigned long long& d,
                                            unsigned long long a,
                                            unsigned long long b) {
    asm("fma.rn.f32x2 %0, %1, %2, %0;" : "+l"(d) : "l"(a), "l"(b));
}
static __device__ __forceinline__ unsigned long long mul2(unsigned long long a,
                                                          unsigned long long b) {
    unsigned long long r;
    asm("mul.rn.f32x2 %0, %1, %2;" : "=l"(r) : "l"(a), "l"(b));
    return r;
}
static __device__ __forceinline__ float2 up2(unsigned long long a) {
    float2 f;
    asm("mov.b64 {%0,%1}, %2;" : "=f"(f.x), "=f"(f.y) : "l"(a));
    return f;
}

__global__ __launch_bounds__(256, 1)
void fa_reg_kernel(const float* __restrict__ q,
                   const float* __restrict__ kv,
                   float* __restrict__ out)
{
    extern __shared__ float sm[];
    const int tid = threadIdx.x;
    const int q0  = blockIdx.x * TQ;
    const int h   = blockIdx.y;
    const int b   = blockIdx.z;

    // QK mapping: 16x16 grid of 8q x 8k tiles
    const int tx = tid & 15;      // key block
    const int ty = tid >> 4;      // query block
    // PV mapping: 8 d-blocks x 16 q-blocks, 2 k-halves
    const int pos  = tid & 127;
    const int half = tid >> 7;
    const int u = pos & 7;        // d block (8 dims)
    const int v = pos >> 3;       // q block (8 rows)

    // ---- load Q tile (scaled) ----
    const float* qb = q + (((size_t)b * SEQ + q0) * NH + h) * DIM;
    #pragma unroll
    for (int it = 0; it < 8; it++) {
        int idx = tid + it * 256;          // 2048 float4
        int r = idx >> 4, c = idx & 15;
        float4 t = *reinterpret_cast<const float4*>(qb + (size_t)r * NH * DIM + c * 4);
        t.x *= SCALE; t.y *= SCALE; t.z *= SCALE; t.w *= SCALE;
        *reinterpret_cast<float4*>(sm + OQ + ixq(r, c)) = t;
    }

    float m_[8], l_[8];
    #pragma unroll
    for (int i = 0; i < 8; i++) { m_[i] = -1e30f; l_[i] = 0.f; }
    unsigned long long O2[8][4];
    #pragma unroll
    for (int i = 0; i < 8; i++)
        #pragma unroll
        for (int dp = 0; dp < 4; dp++) O2[i][dp] = 0ull;

    int kt0 = q0 - WIN;      if (kt0 < 0)   kt0 = 0;
    int kt1 = q0 + TQ + WIN; if (kt1 > SEQ) kt1 = SEQ;

    for (int k0 = kt0; k0 < kt1; k0 += TK) {
        __syncthreads();   // guard K/V/P reuse
        // ---- load K,V tile ----
        const float* kb = kv + ((((size_t)b * SEQ + k0) * 2) * NH + h) * DIM;
        const float* vb = kb + NH * DIM;
        #pragma unroll
        for (int it = 0; it < 8; it++) {
            int idx = tid + it * 256;
            int r = idx >> 4, c = idx & 15;
            size_t go = (size_t)r * 2 * NH * DIM + c * 4;
            *reinterpret_cast<float4*>(sm + OK + ixq(r, c)) =
                *reinterpret_cast<const float4*>(kb + go);
            *reinterpret_cast<float4*>(sm + OV + ixq(r, c)) =
                *reinterpret_cast<const float4*>(vb + go);
        }
        __syncthreads();

        // ---- QK: s[8][8] ----
        float s[8][8];
        #pragma unroll
        for (int i = 0; i < 8; i++)
            #pragma unroll
            for (int j = 0; j < 8; j++) s[i][j] = 0.f;

        const float* Qrow[8];
        const float* Krow[8];
        #pragma unroll
        for (int i = 0; i < 8; i++) {
            Qrow[i] = sm + OQ + (ty * 8 + i) * 64;
            Krow[i] = sm + OK + (tx * 8 + i) * 64;
        }
        const int xq = (ty & 7) * 4;   // float offset of xor
        const int xk = (tx & 7) * 4;

        #pragma unroll 1
        for (int d4 = 0; d4 < 16; d4++) {
            float4 qv[8], kr[8];
            const int oq = ((d4 * 4) ^ xq);
            const int ok = ((d4 * 4) ^ xk);
            #pragma unroll
            for (int i = 0; i < 8; i++)
                qv[i] = *reinterpret_cast<const float4*>(Qrow[i] + oq);
            #pragma unroll
            for (int j = 0; j < 8; j++)
                kr[j] = *reinterpret_cast<const float4*>(Krow[j] + ok);
            #pragma unroll
            for (int i = 0; i < 8; i++)
                #pragma unroll
                for (int j = 0; j < 8; j++)
                    s[i][j] = fmaf(qv[i].x, kr[j].x,
                              fmaf(qv[i].y, kr[j].y,
                              fmaf(qv[i].z, kr[j].z,
                              fmaf(qv[i].w, kr[j].w, s[i][j]))));
        }

        // ---- window mask (only outermost tiles need it) ----
        int dq = k0 - q0;
        if (dq < -128 || dq > 128) {
            #pragma unroll
            for (int i = 0; i < 8; i++) {
                int base = (k0 + tx * 8) - (q0 + ty * 8 + i);
                #pragma unroll
                for (int j = 0; j < 8; j++) {
                    int d = base + j;
                    if (d < -WIN || d > WIN) s[i][j] = -1e30f;
                }
            }
        }

        // ---- online softmax (reduce across 16 tx lanes) ----
        #pragma unroll
        for (int i = 0; i < 8; i++) {
            float tm = s[i][0];
            #pragma unroll
            for (int j = 1; j < 8; j++) tm = fmaxf(tm, s[i][j]);
            tm = fmaxf(tm, __shfl_xor_sync(0xffffffffu, tm, 1));
            tm = fmaxf(tm, __shfl_xor_sync(0xffffffffu, tm, 2));
            tm = fmaxf(tm, __shfl_xor_sync(0xffffffffu, tm, 4));
            tm = fmaxf(tm, __shfl_xor_sync(0xffffffffu, tm, 8));
            float mn = fmaxf(m_[i], tm);
            float corr = __expf(m_[i] - mn);
            m_[i] = mn;
            float ls = 0.f;
            #pragma unroll
            for (int j = 0; j < 8; j++) {
                float p = __expf(s[i][j] - mn);
                s[i][j] = p;
                ls += p;
            }
            ls += __shfl_xor_sync(0xffffffffu, ls, 1);
            ls += __shfl_xor_sync(0xffffffffu, ls, 2);
            ls += __shfl_xor_sync(0xffffffffu, ls, 4);
            ls += __shfl_xor_sync(0xffffffffu, ls, 8);
            l_[i] = l_[i] * corr + ls;
            if (tx == 0) sm[OC + ty * 8 + i] = corr;
        }

        // ---- write P_T[k][q] ----
        #pragma unroll
        for (int j = 0; j < 8; j++) {
            int row = tx * 8 + j;
            float4 a = make_float4(s[0][j], s[1][j], s[2][j], s[3][j]);
            float4 c = make_float4(s[4][j], s[5][j], s[6][j], s[7][j]);
            *reinterpret_cast<float4*>(sm + OP + ixp(row, ty * 2))     = a;
            *reinterpret_cast<float4*>(sm + OP + ixp(row, ty * 2 + 1)) = c;
        }
        __syncthreads();

        // ---- PV: O2 = O2*corr + P^T V  (split-K halves) ----
        #pragma unroll
        for (int i = 0; i < 8; i++) {
            unsigned long long cc = pk2(sm[OC + v * 8 + i]);
            #pragma unroll
            for (int dp = 0; dp < 4; dp++) O2[i][dp] = mul2(O2[i][dp], cc);
        }
        const int kbase = half * 64;
        const int xp = (v * 2);
        const int xv = (u * 2);
        #pragma unroll 1
        for (int kk = 0; kk < 64; kk++) {
            int krow = kbase + kk;
            int xr = (krow >> 3) & 7;
            float4 pa = *reinterpret_cast<const float4*>(sm + OP + (krow * 32 + (xp ^ xr)) * 4);
            float4 pb = *reinterpret_cast<const float4*>(sm + OP + (krow * 32 + ((xp + 1) ^ xr)) * 4);
            ulonglong2 va = *reinterpret_cast<const ulonglong2*>(sm + OV + (krow * 16 + (xv ^ xr)) * 4);
            ulonglong2 vb2 = *reinterpret_cast<const ulonglong2*>(sm + OV + (krow * 16 + ((xv + 1) ^ xr)) * 4);
            float pf[8] = {pa.x, pa.y, pa.z, pa.w, pb.x, pb.y, pb.z, pb.w};
            #pragma unroll
            for (int i = 0; i < 8; i++) {
                unsigned long long pp = pk2(pf[i]);
                fma2(O2[i][0], pp, va.x);
                fma2(O2[i][1], pp, va.y);
                fma2(O2[i][2], pp, vb2.x);
                fma2(O2[i][3], pp, vb2.y);
            }
        }
    }

    // ---- linv ----
    if (tx == 0) {
        #pragma unroll
        for (int i = 0; i < 8; i++) sm[OL + ty * 8 + i] = 1.0f / l_[i];
    }
    __syncthreads();

    // ---- merge halves (stage half1's O in P_T region) ----
    if (half == 1) {
        float* st = sm + OP + pos * 64;
        #pragma unroll
        for (int i = 0; i < 8; i++)
            #pragma unroll
            for (int dp = 0; dp < 4; dp++) {
                float2 f = up2(O2[i][dp]);
                st[i * 8 + dp * 2]     = f.x;
                st[i * 8 + dp * 2 + 1] = f.y;
            }
    }
    __syncthreads();

    if (half == 0) {
        const float* st = sm + OP + pos * 64;
        float* ob = out + (((size_t)b * SEQ + q0 + v * 8) * NH + h) * DIM + u * 8;
        #pragma unroll
        for (int i = 0; i < 8; i++) {
            float li = sm[OL + v * 8 + i];
            float o[8];
            #pragma unroll
            for (int dp = 0; dp < 4; dp++) {
                float2 f = up2(O2[i][dp]);
                o[dp * 2]     = (f.x + st[i * 8 + dp * 2])     * li;
                o[dp * 2 + 1] = (f.y + st[i * 8 + dp * 2 + 1]) * li;
            }
            float* orow = ob + (size_t)i * NH * DIM;
            *reinterpret_cast<float4*>(orow)     = make_float4(o[0], o[1], o[2], o[3]);
            *reinterpret_cast<float4*>(orow + 4) = make_float4(o[4], o[5], o[6], o[7]);
        }
    }
}

extern "C" void kernel_launch(void* const* d_in, const int* in_sizes, int n_in,
                              void* d_out, int out_size)
{
    const float* q  = (const float*)d_in[0];
    const float* kv = (const float*)d_in[1];
    float* out = (float*)d_out;

    int B = in_sizes[0] / (SEQ * NH * DIM);

    size_t smem = (size_t)SMF * sizeof(float);   // 164864 B
    cudaFuncSetAttribute(fa_reg_kernel,
                         cudaFuncAttributeMaxDynamicSharedMemorySize, (int)smem);

    dim3 grid(SEQ / TQ, NH, B);
    fa_reg_kernel<<<grid, 256, smem>>>(q, kv, out);
}

// round 4
// speedup vs baseline: 2.2385x; 1.0827x over previous
#include <cuda_runtime.h>
#include <stdint.h>

// FlashCrossAttentionV2 SIMT, both GEMMs on packed fma.rn.f32x2.
// B=2, Sq=Sk=2048, H=16, D=64, window=(256,256), fp32.
// CTA: 256 threads, TQ=128, TK=128 (<=5 tiles in window).
// QK: 16x16 thread grid, 8q x 8k tile, packed over k (K transposed in smem).
//     Thread tx owns keys {4tx..4tx+3} u {64+4tx..64+4tx+3}.
// PV: 8d x 16q blocks x 2 k-halves, packed over d.

#define SEQ  2048
#define NH   16
#define DIM  64
#define WIN  256
#define TQ   128
#define TK   128
#define SCALE 0.125f

// smem float offsets
#define OQ  0          // Q: 128 x 64 (ixq swizzle)
#define OKT 8192       // Kt: 64(d) x 128(k), chunk-swizzled
#define OV  16384      // V: 128 x 64 (ixq swizzle)
#define OP  24576      // P_T: 128(k) x 128(q) (ixp swizzle; also merge staging)
#define OC  40960      // corr[128]
#define OL  41088      // linv[128]
#define SMF 41216      // -> 164864 bytes

static __device__ __forceinline__ int ixq(int r, int g) {
    return (r * 16 + (g ^ ((r >> 3) & 7))) * 4;
}
static __device__ __forceinline__ int ixp(int r, int g) {
    return (r * 32 + (g ^ ((r >> 3) & 7))) * 4;
}

static __device__ __forceinline__ unsigned long long pk2(float x) {
    unsigned long long r;
    asm("mov.b64 %0, {%1,%1};" : "=l"(r) : "f"(x));
    return r;
}
static __device__ __forceinline__ void fma2(unsigned long long& d,
                                            unsigned long long a,
                                            unsigned long long b) {
    asm("fma.rn.f32x2 %0, %1, %2, %0;" : "+l"(d) : "l"(a), "l"(b));
}
static __device__ __forceinline__ unsigned long long mul2(unsigned long long a,
                                                          unsigned long long b) {
    unsigned long long r;
    asm("mul.rn.f32x2 %0, %1, %2;" : "=l"(r) : "l"(a), "l"(b));
    return r;
}
static __device__ __forceinline__ float2 up2(unsigned long long a) {
    float2 f;
    asm("mov.b64 {%0,%1}, %2;" : "=f"(f.x), "=f"(f.y) : "l"(a));
    return f;
}

__global__ __launch_bounds__(256, 1)
void fa_pk_kernel(const float* __restrict__ q,
                  const float* __restrict__ kv,
                  float* __restrict__ out)
{
    extern __shared__ float sm[];
    const int tid = threadIdx.x;
    const int q0  = blockIdx.x * TQ;
    const int h   = blockIdx.y;
    const int b   = blockIdx.z;

    const int tx = tid & 15;      // key block
    const int ty = tid >> 4;      // query block
    const int pos  = tid & 127;   // PV mapping
    const int half = tid >> 7;
    const int u = pos & 7;        // d block
    const int v = pos >> 3;       // q block

    // ---- load Q tile (scaled) ----
    const float* qb = q + (((size_t)b * SEQ + q0) * NH + h) * DIM;
    #pragma unroll
    for (int it = 0; it < 8; it++) {
        int idx = tid + it * 256;
        int r = idx >> 4, c = idx & 15;
        float4 t = *reinterpret_cast<const float4*>(qb + (size_t)r * NH * DIM + c * 4);
        t.x *= SCALE; t.y *= SCALE; t.z *= SCALE; t.w *= SCALE;
        *reinterpret_cast<float4*>(sm + OQ + ixq(r, c)) = t;
    }

    float m_[8], l_[8];
    #pragma unroll
    for (int i = 0; i < 8; i++) { m_[i] = -1e30f; l_[i] = 0.f; }
    unsigned long long O2[8][4];
    #pragma unroll
    for (int i = 0; i < 8; i++)
        #pragma unroll
        for (int dp = 0; dp < 4; dp++) O2[i][dp] = 0ull;

    int kt0 = q0 - WIN;      if (kt0 < 0)   kt0 = 0;
    int kt1 = q0 + TQ + WIN; if (kt1 > SEQ) kt1 = SEQ;

    for (int k0 = kt0; k0 < kt1; k0 += TK) {
        __syncthreads();
        // ---- load K (transposed into Kt) and V ----
        const float* kb = kv + ((((size_t)b * SEQ + k0) * 2) * NH + h) * DIM;
        const float* vb = kb + NH * DIM;
        #pragma unroll
        for (int it = 0; it < 8; it++) {
            int idx = tid + it * 256;
            int r = idx >> 4, c = idx & 15;
            size_t go = (size_t)r * 2 * NH * DIM + c * 4;
            float4 kt4 = *reinterpret_cast<const float4*>(kb + go);
            // scatter transposed: Kt[d=4c+j][k=r], chunk swizz ch=(r>>2)^c
            int ch = ((r >> 2) ^ c) * 4 + (r & 3);
            sm[OKT + (c * 4 + 0) * 128 + ch] = kt4.x;
            sm[OKT + (c * 4 + 1) * 128 + ch] = kt4.y;
            sm[OKT + (c * 4 + 2) * 128 + ch] = kt4.z;
            sm[OKT + (c * 4 + 3) * 128 + ch] = kt4.w;
            *reinterpret_cast<float4*>(sm + OV + ixq(r, c)) =
                *reinterpret_cast<const float4*>(vb + go);
        }
        __syncthreads();

        // ---- QK packed over k: s2[8][4] (pairs) ----
        unsigned long long s2[8][4];
        #pragma unroll
        for (int i = 0; i < 8; i++)
            #pragma unroll
            for (int jp = 0; jp < 4; jp++) s2[i][jp] = 0ull;

        const float* Qrow[8];
        #pragma unroll
        for (int i = 0; i < 8; i++) Qrow[i] = sm + OQ + (ty * 8 + i) * 64;
        const int xq = (ty & 7) * 4;

        #pragma unroll 1
        for (int dc = 0; dc < 16; dc++) {     // 4 d per iter
            float4 qv[8];
            const int oq = (dc * 4) ^ xq;
            #pragma unroll
            for (int i = 0; i < 8; i++)
                qv[i] = *reinterpret_cast<const float4*>(Qrow[i] + oq);
            const int chA = (tx ^ dc) * 4;           // low k chunk (float off)
            const float* ktb = sm + OKT + dc * 512;  // 4 rows of 128
            #pragma unroll
            for (int dd = 0; dd < 4; dd++) {
                ulonglong2 kA = *reinterpret_cast<const ulonglong2*>(ktb + dd * 128 + chA);
                ulonglong2 kB = *reinterpret_cast<const ulonglong2*>(ktb + dd * 128 + chA + 64);
                #pragma unroll
                for (int i = 0; i < 8; i++) {
                    unsigned long long qp = pk2(((const float*)&qv[i])[dd]);
                    fma2(s2[i][0], qp, kA.x);
                    fma2(s2[i][1], qp, kA.y);
                    fma2(s2[i][2], qp, kB.x);
                    fma2(s2[i][3], qp, kB.y);
                }
            }
        }

        // ---- unpack ----
        float s[8][8];
        #pragma unroll
        for (int i = 0; i < 8; i++) {
            #pragma unroll
            for (int jp = 0; jp < 4; jp++) {
                float2 f = up2(s2[i][jp]);
                s[i][jp * 2]     = f.x;
                s[i][jp * 2 + 1] = f.y;
            }
        }
        // local j -> key offset within tile:
        //   j<4 : tx*4 + j ;  j>=4 : 64 + tx*4 + (j-4)

        // ---- window mask (outermost tiles only) ----
        int dq = k0 - q0;
        if (dq < -128 || dq > 128) {
            #pragma unroll
            for (int i = 0; i < 8; i++) {
                int qrow = q0 + ty * 8 + i;
                #pragma unroll
                for (int j = 0; j < 8; j++) {
                    int kloc = (j < 4) ? (tx * 4 + j) : (64 + tx * 4 + j - 4);
                    int d = (k0 + kloc) - qrow;
                    if (d < -WIN || d > WIN) s[i][j] = -1e30f;
                }
            }
        }

        // ---- online softmax (reduce across 16 tx lanes) ----
        #pragma unroll
        for (int i = 0; i < 8; i++) {
            float tm = s[i][0];
            #pragma unroll
            for (int j = 1; j < 8; j++) tm = fmaxf(tm, s[i][j]);
            tm = fmaxf(tm, __shfl_xor_sync(0xffffffffu, tm, 1));
            tm = fmaxf(tm, __shfl_xor_sync(0xffffffffu, tm, 2));
            tm = fmaxf(tm, __shfl_xor_sync(0xffffffffu, tm, 4));
            tm = fmaxf(tm, __shfl_xor_sync(0xffffffffu, tm, 8));
            float mn = fmaxf(m_[i], tm);
            float corr = __expf(m_[i] - mn);
            m_[i] = mn;
            float ls = 0.f;
            #pragma unroll
            for (int j = 0; j < 8; j++) {
                float p = __expf(s[i][j] - mn);
                s[i][j] = p;
                ls += p;
            }
            ls += __shfl_xor_sync(0xffffffffu, ls, 1);
            ls += __shfl_xor_sync(0xffffffffu, ls, 2);
            ls += __shfl_xor_sync(0xffffffffu, ls, 4);
            ls += __shfl_xor_sync(0xffffffffu, ls, 8);
            l_[i] = l_[i] * corr + ls;
            if (tx == 0) sm[OC + ty * 8 + i] = corr;
        }

        // ---- write P_T[k][q] ----
        #pragma unroll
        for (int j = 0; j < 8; j++) {
            int row = (j < 4) ? (tx * 4 + j) : (64 + tx * 4 + j - 4);
            float4 a = make_float4(s[0][j], s[1][j], s[2][j], s[3][j]);
            float4 c = make_float4(s[4][j], s[5][j], s[6][j], s[7][j]);
            *reinterpret_cast<float4*>(sm + OP + ixp(row, ty * 2))     = a;
            *reinterpret_cast<float4*>(sm + OP + ixp(row, ty * 2 + 1)) = c;
        }
        __syncthreads();

        // ---- PV: O2 = O2*corr + P^T V (split-K halves, packed over d) ----
        #pragma unroll
        for (int i = 0; i < 8; i++) {
            unsigned long long cc = pk2(sm[OC + v * 8 + i]);
            #pragma unroll
            for (int dp = 0; dp < 4; dp++) O2[i][dp] = mul2(O2[i][dp], cc);
        }
        const int kbase = half * 64;
        const int xp = v * 2;
        const int xv = u * 2;
        #pragma unroll 1
        for (int kk = 0; kk < 64; kk++) {
            int krow = kbase + kk;
            int xr = (krow >> 3) & 7;
            float4 pa = *reinterpret_cast<const float4*>(sm + OP + (krow * 32 + (xp ^ xr)) * 4);
            float4 pb = *reinterpret_cast<const float4*>(sm + OP + (krow * 32 + ((xp + 1) ^ xr)) * 4);
            ulonglong2 va  = *reinterpret_cast<const ulonglong2*>(sm + OV + (krow * 16 + (xv ^ xr)) * 4);
            ulonglong2 vb2 = *reinterpret_cast<const ulonglong2*>(sm + OV + (krow * 16 + ((xv + 1) ^ xr)) * 4);
            float pf[8] = {pa.x, pa.y, pa.z, pa.w, pb.x, pb.y, pb.z, pb.w};
            #pragma unroll
            for (int i = 0; i < 8; i++) {
                unsigned long long pp = pk2(pf[i]);
                fma2(O2[i][0], pp, va.x);
                fma2(O2[i][1], pp, va.y);
                fma2(O2[i][2], pp, vb2.x);
                fma2(O2[i][3], pp, vb2.y);
            }
        }
    }

    // ---- linv ----
    if (tx == 0) {
        #pragma unroll
        for (int i = 0; i < 8; i++) sm[OL + ty * 8 + i] = 1.0f / l_[i];
    }
    __syncthreads();

    // ---- merge halves (stage half1's O in P_T region) ----
    if (half == 1) {
        float* st = sm + OP + pos * 64;
        #pragma unroll
        for (int i = 0; i < 8; i++)
            #pragma unroll
            for (int dp = 0; dp < 4; dp++) {
                float2 f = up2(O2[i][dp]);
                st[i * 8 + dp * 2]     = f.x;
                st[i * 8 + dp * 2 + 1] = f.y;
            }
    }
    __syncthreads();

    if (half == 0) {
        const float* st = sm + OP + pos * 64;
        float* ob = out + (((size_t)b * SEQ + q0 + v * 8) * NH + h) * DIM + u * 8;
        #pragma unroll
        for (int i = 0; i < 8; i++) {
            float li = sm[OL + v * 8 + i];
            float o[8];
            #pragma unroll
            for (int dp = 0; dp < 4; dp++) {
                float2 f = up2(O2[i][dp]);
                o[dp * 2]     = (f.x + st[i * 8 + dp * 2])     * li;
                o[dp * 2 + 1] = (f.y + st[i * 8 + dp * 2 + 1]) * li;
            }
            float* orow = ob + (size_t)i * NH * DIM;
            *reinterpret_cast<float4*>(orow)     = make_float4(o[0], o[1], o[2], o[3]);
            *reinterpret_cast<float4*>(orow + 4) = make_float4(o[4], o[5], o[6], o[7]);
        }
    }
}

extern "C" void kernel_launch(void* const* d_in, const int* in_sizes, int n_in,
                              void* d_out, int out_size)
{
    const float* q  = (const float*)d_in[0];
    const float* kv = (const float*)d_in[1];
    float* out = (float*)d_out;

    int B = in_sizes[0] / (SEQ * NH * DIM);

    size_t smem = (size_t)SMF * sizeof(float);   // 164864 B
    cudaFuncSetAttribute(fa_pk_kernel,
                         cudaFuncAttributeMaxDynamicSharedMemorySize, (int)smem);

    dim3 grid(SEQ / TQ, NH, B);
    fa_pk_kernel<<<grid, 256, smem>>>(q, kv, out);
}